// round 12
// baseline (speedup 1.0000x reference)
#include <cuda_runtime.h>
#include <cuda_bf16.h>
#include <cstdint>

#define BB 1024
#define TT 200

// ---------------- scratch (device globals; no allocation allowed) ----------------
__device__ float g_WhistT[256 * 128];   // [j][k] : (W1b - W1c)^T
__device__ float g_WmulT [256 * 128];   // [j][k] : W1d^T
__device__ float g_Wcur  [128 * 256];   // [k][j] : W1a + W1c
__device__ __align__(16) __nv_bfloat16 g_W2Tb[128 * 256]; // [j2][k] bf16 lau_w2^T (row-major)
__device__ float g_W1Tm  [512 * 448];   // [j][k] : mlp_w1^T
__device__ float g_W2Tm  [256 * 512];   // [j][k] : mlp_w2^T
__device__ float g_cur[BB * 128];
__device__ float g_cb [BB * 256];
__device__ float g_hist[(size_t)BB * TT * 128];
__device__ float g_aw [BB * TT];
__device__ float g_x  [BB * 448];
__device__ float g_z1 [BB * 512];
__device__ float g_z2 [BB * 256];
__device__ float g_a0[448], g_bp0[448];
__device__ float g_a1[512], g_bp1[512];
__device__ float g_a2[256], g_bp2[256];

// ---------------- warp-MMA helpers (sm_80-era PTX, legal on compute_103) ----------------
__device__ __forceinline__ uint32_t smem_u32(const void* p) {
    uint32_t a;
    asm("{ .reg .u64 t; cvta.to.shared.u64 t, %1; cvt.u32.u64 %0, t; }" : "=r"(a) : "l"(p));
    return a;
}
__device__ __forceinline__ void mma_bf16(float* c, const uint32_t* a, const uint32_t* b) {
    asm volatile("mma.sync.aligned.m16n8k16.row.col.f32.bf16.bf16.f32 "
        "{%0,%1,%2,%3}, {%4,%5,%6,%7}, {%8,%9}, {%0,%1,%2,%3};"
        : "+f"(c[0]), "+f"(c[1]), "+f"(c[2]), "+f"(c[3])
        : "r"(a[0]), "r"(a[1]), "r"(a[2]), "r"(a[3]), "r"(b[0]), "r"(b[1]));
}
__device__ __forceinline__ void ldsm4(uint32_t* r, uint32_t addr) {
    asm volatile("ldmatrix.sync.aligned.m8n8.x4.shared.b16 {%0,%1,%2,%3}, [%4];"
        : "=r"(r[0]), "=r"(r[1]), "=r"(r[2]), "=r"(r[3]) : "r"(addr));
}

// ---------------- prep: fold & transpose weights ----------------
__global__ void k_prep(const float* __restrict__ w1, const float* __restrict__ w2,
                       const float* __restrict__ mw1, const float* __restrict__ mw2) {
    int idx0 = blockIdx.x * blockDim.x + threadIdx.x;
    int stride = gridDim.x * blockDim.x;
    for (int i = idx0; i < 256 * 128; i += stride) {
        int j = i >> 7, k = i & 127;
        g_WhistT[i] = w1[(128 + k) * 256 + j] - w1[(256 + k) * 256 + j];
        g_WmulT[i]  = w1[(384 + k) * 256 + j];
    }
    for (int i = idx0; i < 128 * 256; i += stride) {
        int k = i >> 8, j = i & 255;
        g_Wcur[i] = w1[k * 256 + j] + w1[(256 + k) * 256 + j];
    }
    for (int i = idx0; i < 128 * 256; i += stride) {
        int j2 = i >> 8, k = i & 255;
        g_W2Tb[j2 * 256 + k] = __float2bfloat16_rn(w2[k * 128 + j2]);
    }
    for (int i = idx0; i < 512 * 448; i += stride) {
        int j = i / 448, k = i - j * 448;
        g_W1Tm[i] = mw1[k * 512 + j];
    }
    for (int i = idx0; i < 256 * 512; i += stride) {
        int j = i >> 9, k = i & 511;
        g_W2Tm[i] = mw2[k * 256 + j];
    }
}

// ---------------- cur gather + per-batch folded bias cb ----------------
__global__ void __launch_bounds__(256) k_curcb(const int* __restrict__ mid, const int* __restrict__ cat,
                                               const float* __restrict__ mtab, const float* __restrict__ ctab,
                                               const float* __restrict__ b1) {
    __shared__ float sc[128];
    int b = blockIdx.x, tid = threadIdx.x;
    if (tid < 128) {
        float v = (tid < 64) ? mtab[(size_t)mid[b] * 64 + tid]
                             : ctab[(size_t)cat[b] * 64 + (tid - 64)];
        sc[tid] = v;
        g_cur[b * 128 + tid] = v;
    }
    __syncthreads();
    float acc = b1[tid];
#pragma unroll 8
    for (int k = 0; k < 128; k++) acc += sc[k] * g_Wcur[k * 256 + tid];
    g_cb[b * 256 + tid] = acc;
}

// ---------------- fused LAU via warp MMA (HMMA), 7 warps x 2 m-tiles: B-fragment reuse ----------------
// smem: sA  hist bf16 [224 rows][stride 136 bf16 = 272B]         @ 0      (60,928)
//       sB  Weff^T bf16 [256 rows j][stride 136]                 @ 60928  (69,632)
//       sW2 lau_w2^T bf16 [128 rows j2][stride 264 bf16 = 528B]  @ 130560 (67,584)
//       misc fp32: cb[256] b2[128]@256 w3[128]@384 b3@512 cur[128]@528 @ 198144
#define SM_A    0
#define SM_B    60928
#define SM_W2   130560
#define SM_MISC 198144
#define SMEM_G  200768
#define NTL 224

__global__ void __launch_bounds__(NTL, 1)
k_lau_mma(const int* __restrict__ hm, const int* __restrict__ hc,
          const float* __restrict__ mtab, const float* __restrict__ ctab,
          const float* __restrict__ b2p, const float* __restrict__ w3p,
          const float* __restrict__ b3p) {
    extern __shared__ char smc[];
    uint32_t sb = smem_u32(smc);
    int b = blockIdx.x, tid = threadIdx.x;
    int wid = tid >> 5, lane = tid & 31;
    float* misc = (float*)(smc + SM_MISC);

    // phase 0: misc
    for (int i = tid; i < 256; i += NTL) misc[i] = g_cb[b * 256 + i];
    if (tid < 128) {
        misc[256 + tid] = b2p[tid];
        misc[384 + tid] = w3p[tid];
        misc[528 + tid] = g_cur[b * 128 + tid];
    }
    if (tid == 0) misc[512] = b3p[0];
    __syncthreads();

    // sW2 copy (u32 pairs)
    {
        const uint32_t* src = (const uint32_t*)g_W2Tb;
        for (int i = tid; i < 128 * 128; i += NTL) {
            int j2 = i >> 7, kp = i & 127;
            *(uint32_t*)(smc + SM_W2 + j2 * 528 + kp * 4) = src[i];
        }
    }
    // sB: Weff^T[j][k] = WhistT + cur[k]*WmulT, bf16
    for (int i = tid; i < 256 * 64; i += NTL) {
        int j = i >> 6, kp = i & 63, k = kp * 2;
        float c0 = misc[528 + k], c1 = misc[528 + k + 1];
        float v0 = g_WhistT[j * 128 + k]     + c0 * g_WmulT[j * 128 + k];
        float v1 = g_WhistT[j * 128 + k + 1] + c1 * g_WmulT[j * 128 + k + 1];
        __nv_bfloat162 p = __floats2bfloat162_rn(v0, v1);
        *(uint32_t*)(smc + SM_B + j * 272 + kp * 4) = *(uint32_t*)&p;
    }
    // hist gather: fp32 -> g_hist, bf16 -> sA
    const int* hmb = hm + b * TT;
    const int* hcb = hc + b * TT;
    for (int i = tid; i < TT * 32; i += NTL) {
        int t = i >> 5, c4 = i & 31;
        float4 v = (c4 < 16) ? ((const float4*)(mtab + (size_t)hmb[t] * 64))[c4]
                             : ((const float4*)(ctab + (size_t)hcb[t] * 64))[c4 - 16];
        ((float4*)(g_hist + ((size_t)b * TT + t) * 128))[c4] = v;
        __nv_bfloat162 p0 = __floats2bfloat162_rn(v.x, v.y);
        __nv_bfloat162 p1 = __floats2bfloat162_rn(v.z, v.w);
        uint2 u; u.x = *(uint32_t*)&p0; u.y = *(uint32_t*)&p1;
        *(uint2*)(smc + SM_A + t * 272 + c4 * 8) = u;
    }
    // zero pad rows 200..223 (24 rows * 272B = 6528B = 408 uint4)
    for (int i = tid; i < 408; i += NTL)
        ((uint4*)(smc + SM_A + 200 * 272))[i] = make_uint4(0, 0, 0, 0);
    __syncthreads();

    // per-lane ldmatrix base addresses
    uint32_t aBase  = sb + SM_A  + (lane & 7) * 272 + ((lane >> 3) & 1) * (8 * 272) + ((lane >> 4) & 1) * 16;
    uint32_t bBase4 = sb + SM_B  + (lane & 7) * 272 + ((lane >> 3) & 1) * 16 + ((lane >> 4) & 1) * (8 * 272);
    uint32_t wBase4 = sb + SM_W2 + (lane & 7) * 528 + ((lane >> 3) & 1) * 16 + ((lane >> 4) & 1) * (8 * 528);

    // warp wid handles m-tiles 2*wid and 2*wid+1 (tile 13 = zero padding)
    int mt0 = 2 * wid, mt1 = 2 * wid + 1;
    uint32_t aRow0 = aBase + mt0 * (16 * 272);
    uint32_t aRow1 = aBase + mt1 * (16 * 272);

    float acc2a[16][4], acc2b[16][4];
#pragma unroll
    for (int i = 0; i < 16; i++) {
        acc2a[i][0] = acc2a[i][1] = acc2a[i][2] = acc2a[i][3] = 0.f;
        acc2b[i][0] = acc2b[i][1] = acc2b[i][2] = acc2b[i][3] = 0.f;
    }

#pragma unroll
    for (int h = 0; h < 2; h++) {
#pragma unroll
        for (int q = 0; q < 2; q++) {
            // GEMM1 quarter: N cols [h*128+q*64, +64), K=128; both m-tiles share B
            float acc1a[8][4], acc1b[8][4];
#pragma unroll
            for (int i = 0; i < 8; i++) {
                acc1a[i][0] = acc1a[i][1] = acc1a[i][2] = acc1a[i][3] = 0.f;
                acc1b[i][0] = acc1b[i][1] = acc1b[i][2] = acc1b[i][3] = 0.f;
            }
            uint32_t bQ = bBase4 + (h * 128 + q * 64) * 272;
#pragma unroll
            for (int k0 = 0; k0 < 128; k0 += 16) {
                uint32_t a0[4], a1[4];
                ldsm4(a0, aRow0 + k0 * 2);
                ldsm4(a1, aRow1 + k0 * 2);
#pragma unroll
                for (int p = 0; p < 4; p++) {
                    uint32_t bf[4];
                    ldsm4(bf, bQ + p * (16 * 272) + k0 * 2);
                    mma_bf16(acc1a[2 * p],     a0, bf);
                    mma_bf16(acc1a[2 * p + 1], a0, bf + 2);
                    mma_bf16(acc1b[2 * p],     a1, bf);
                    mma_bf16(acc1b[2 * p + 1], a1, bf + 2);
                }
            }
            // sigmoid + pack to A-fragments for GEMM2 (fragment layouts coincide)
            uint32_t hba[16], hbb[16];
#pragma unroll
            for (int ns = 0; ns < 8; ns++) {
                int n = h * 128 + q * 64 + ns * 8 + (lane & 3) * 2;
                float cb0 = misc[n], cb1 = misc[n + 1];
                {
                    float s0 = 1.f / (1.f + __expf(-(acc1a[ns][0] + cb0)));
                    float s1 = 1.f / (1.f + __expf(-(acc1a[ns][1] + cb1)));
                    float s2 = 1.f / (1.f + __expf(-(acc1a[ns][2] + cb0)));
                    float s3 = 1.f / (1.f + __expf(-(acc1a[ns][3] + cb1)));
                    __nv_bfloat162 p0 = __floats2bfloat162_rn(s0, s1);
                    __nv_bfloat162 p1 = __floats2bfloat162_rn(s2, s3);
                    hba[ns * 2]     = *(uint32_t*)&p0;
                    hba[ns * 2 + 1] = *(uint32_t*)&p1;
                }
                {
                    float s0 = 1.f / (1.f + __expf(-(acc1b[ns][0] + cb0)));
                    float s1 = 1.f / (1.f + __expf(-(acc1b[ns][1] + cb1)));
                    float s2 = 1.f / (1.f + __expf(-(acc1b[ns][2] + cb0)));
                    float s3 = 1.f / (1.f + __expf(-(acc1b[ns][3] + cb1)));
                    __nv_bfloat162 p0 = __floats2bfloat162_rn(s0, s1);
                    __nv_bfloat162 p1 = __floats2bfloat162_rn(s2, s3);
                    hbb[ns * 2]     = *(uint32_t*)&p0;
                    hbb[ns * 2 + 1] = *(uint32_t*)&p1;
                }
            }
            // GEMM2 partial: K cols [h*128+q*64, +64) of W2^T, N=128; shared B
#pragma unroll
            for (int ktl = 0; ktl < 4; ktl++) {
                int kt = h * 8 + q * 4 + ktl;
                const uint32_t* a2a = &hba[ktl * 4];
                const uint32_t* a2b = &hbb[ktl * 4];
#pragma unroll
                for (int p2 = 0; p2 < 8; p2++) {
                    uint32_t bf[4];
                    ldsm4(bf, wBase4 + p2 * (16 * 528) + kt * 32);
                    mma_bf16(acc2a[2 * p2],     a2a, bf);
                    mma_bf16(acc2a[2 * p2 + 1], a2a, bf + 2);
                    mma_bf16(acc2b[2 * p2],     a2b, bf);
                    mma_bf16(acc2b[2 * p2 + 1], a2b, bf + 2);
                }
            }
        }
    }
    // epilogue: aw[t] = sum_j sigmoid(h2 + b2)*w3 + b3, for both m-tiles
    float paA = 0.f, pbA = 0.f, paB = 0.f, pbB = 0.f;
#pragma unroll
    for (int ns2 = 0; ns2 < 16; ns2++) {
        int n = ns2 * 8 + (lane & 3) * 2;
        float b20 = misc[256 + n], b21 = misc[256 + n + 1];
        float w30 = misc[384 + n], w31 = misc[384 + n + 1];
        paA += w30 / (1.f + __expf(-(acc2a[ns2][0] + b20)));
        paA += w31 / (1.f + __expf(-(acc2a[ns2][1] + b21)));
        pbA += w30 / (1.f + __expf(-(acc2a[ns2][2] + b20)));
        pbA += w31 / (1.f + __expf(-(acc2a[ns2][3] + b21)));
        paB += w30 / (1.f + __expf(-(acc2b[ns2][0] + b20)));
        paB += w31 / (1.f + __expf(-(acc2b[ns2][1] + b21)));
        pbB += w30 / (1.f + __expf(-(acc2b[ns2][2] + b20)));
        pbB += w31 / (1.f + __expf(-(acc2b[ns2][3] + b21)));
    }
    paA += __shfl_xor_sync(0xffffffffu, paA, 1);
    paA += __shfl_xor_sync(0xffffffffu, paA, 2);
    pbA += __shfl_xor_sync(0xffffffffu, pbA, 1);
    pbA += __shfl_xor_sync(0xffffffffu, pbA, 2);
    paB += __shfl_xor_sync(0xffffffffu, paB, 1);
    paB += __shfl_xor_sync(0xffffffffu, paB, 2);
    pbB += __shfl_xor_sync(0xffffffffu, pbB, 1);
    pbB += __shfl_xor_sync(0xffffffffu, pbB, 2);
    if ((lane & 3) == 0) {
        float b3v = misc[512];
        int t0 = mt0 * 16 + (lane >> 2);
        if (t0 < TT)     g_aw[b * TT + t0]     = paA + b3v;
        if (t0 + 8 < TT) g_aw[b * TT + t0 + 8] = pbA + b3v;
        int t1 = mt1 * 16 + (lane >> 2);
        if (t1 < TT)     g_aw[b * TT + t1]     = paB + b3v;
        if (t1 + 8 < TT) g_aw[b * TT + t1 + 8] = pbB + b3v;
    }
}

// ---------------- softmax + lau + hmean + assemble x ----------------
__global__ void __launch_bounds__(256) k_softlau(const int* __restrict__ mask, const int* __restrict__ uid,
                                                 const float* __restrict__ utab) {
    __shared__ float ssc[200], smf[200], red[256];
    __shared__ float c1[128], c2[128];
    __shared__ float s_mx, s_sum, s_nm;
    int b = blockIdx.x, tid = threadIdx.x;
    float a = -1e30f, mf = 0.f;
    if (tid < 200) {
        int m = mask[b * TT + tid];
        mf = (float)m;
        float v = g_aw[b * TT + tid];
        a = m ? v : -1e30f;
        smf[tid] = mf;
    }
    red[tid] = a; __syncthreads();
    for (int s = 128; s > 0; s >>= 1) { if (tid < s) red[tid] = fmaxf(red[tid], red[tid + s]); __syncthreads(); }
    if (tid == 0) s_mx = red[0];
    __syncthreads();
    float e = (tid < 200 && mf > 0.f) ? __expf(a - s_mx) : 0.f;
    red[tid] = e; __syncthreads();
    for (int s = 128; s > 0; s >>= 1) { if (tid < s) red[tid] += red[tid + s]; __syncthreads(); }
    if (tid == 0) s_sum = red[0];
    __syncthreads();
    red[tid] = mf; __syncthreads();
    for (int s = 128; s > 0; s >>= 1) { if (tid < s) red[tid] += red[tid + s]; __syncthreads(); }
    if (tid == 0) s_nm = red[0];
    __syncthreads();
    if (tid < 200) ssc[tid] = e / s_sum;
    __syncthreads();

    int j = tid & 127, half = tid >> 7;
    float accL = 0.f, accM = 0.f;
    int t0 = half * 100;
    for (int t = t0; t < t0 + 100; t++) {
        float h = g_hist[((size_t)b * TT + t) * 128 + j];
        accL += ssc[t] * h;
        accM += smf[t] * h;
    }
    if (half == 1) { c1[j] = accL; c2[j] = accM; }
    __syncthreads();
    if (tid < 64) g_x[b * 448 + tid] = utab[(size_t)uid[b] * 64 + tid];
    if (half == 0) {
        g_x[b * 448 + 64 + j]  = g_cur[b * 128 + j];
        g_x[b * 448 + 192 + j] = accL + c1[j];
        g_x[b * 448 + 320 + j] = (accM + c2[j]) / s_nm;
    }
}

// ---------------- batch-norm stats, coalesced: 32 features/block ----------------
__global__ void __launch_bounds__(256) k_bnstats(int which, const float* __restrict__ gamma,
                                                 const float* __restrict__ beta) {
    const float* src; float* a; float* bp; int F;
    if (which == 0)      { src = g_x;  a = g_a0; bp = g_bp0; F = 448; }
    else if (which == 1) { src = g_z1; a = g_a1; bp = g_bp1; F = 512; }
    else                 { src = g_z2; a = g_a2; bp = g_bp2; F = 256; }
    __shared__ float sh1[8][33], sh2[8][33];
    int tid = threadIdx.x;
    int fl = tid & 31, rg = tid >> 5;            // 8 row-groups
    int f = blockIdx.x * 32 + fl;
    float s = 0.f, s2 = 0.f;
    for (int r = rg; r < BB; r += 8) {
        float v = src[(size_t)r * F + f];
        s += v; s2 += v * v;
    }
    sh1[rg][fl] = s; sh2[rg][fl] = s2;
    __syncthreads();
    if (rg == 0) {
#pragma unroll
        for (int i = 1; i < 8; i++) { s += sh1[i][fl]; s2 += sh2[i][fl]; }
        float mean = s * (1.f / BB);
        float var = s2 * (1.f / BB) - mean * mean;
        float ai = gamma[f] * rsqrtf(var + 1e-5f);
        a[f] = ai;
        bp[f] = beta[f] - mean * ai;
    }
}

// ---------------- MLP layer 1: z1 = BN0(x) @ W1 + b1  (grid 32 x 4) ----------------
__global__ void __launch_bounds__(256) k_mlp1(const float* __restrict__ b1) {
    extern __shared__ float sm[];
    float* sx = sm;                // 32*448
    float* sa = sx + 32 * 448;     // 448
    float* sb = sa + 448;          // 448
    int rb = blockIdx.x * 32, jb = blockIdx.y * 128, tid = threadIdx.x;
    for (int i = tid; i < 448; i += 256) { sa[i] = g_a0[i]; sb[i] = g_bp0[i]; }
    __syncthreads();
    for (int i = tid; i < 32 * 112; i += 256) {
        int r = i / 112, k4 = i - r * 112;
        float4 v = ((const float4*)(g_x + (size_t)(rb + r) * 448))[k4];
        int k = k4 * 4;
        v.x = v.x * sa[k]     + sb[k];
        v.y = v.y * sa[k + 1] + sb[k + 1];
        v.z = v.z * sa[k + 2] + sb[k + 2];
        v.w = v.w * sa[k + 3] + sb[k + 3];
        ((float4*)(sx + r * 448))[k4] = v;
    }
    __syncthreads();
    int j = jb + (tid & 127);
    int oo = tid >> 7;
    const float4* Wj = (const float4*)(g_W1Tm + (size_t)j * 448);
    float bj = b1[j];
    for (int oi = 0; oi < 2; oi++) {
        int o = oo * 2 + oi;
        float acc[8];
#pragma unroll
        for (int u = 0; u < 8; u++) acc[u] = bj;
#pragma unroll 4
        for (int k4 = 0; k4 < 112; k4++) {
            float4 w = Wj[k4];
#pragma unroll
            for (int u = 0; u < 8; u++) {
                float4 h = ((const float4*)(sx + (o * 8 + u) * 448))[k4];
                acc[u] += w.x * h.x + w.y * h.y + w.z * h.z + w.w * h.w;
            }
        }
#pragma unroll
        for (int u = 0; u < 8; u++)
            g_z1[(size_t)(rb + o * 8 + u) * 512 + j] = acc[u];
    }
}

// ---------------- MLP layer 2: z2 = leaky(BN1(z1)) @ W2 + b2  (grid 32 x 2) ----------------
__global__ void __launch_bounds__(256) k_mlp2(const float* __restrict__ b2) {
    extern __shared__ float sm[];
    float* sy = sm;                // 32*512
    float* sa = sy + 32 * 512;     // 512
    float* sb = sa + 512;          // 512
    int rb = blockIdx.x * 32, jb = blockIdx.y * 128, tid = threadIdx.x;
    for (int i = tid; i < 512; i += 256) { sa[i] = g_a1[i]; sb[i] = g_bp1[i]; }
    __syncthreads();
    for (int i = tid; i < 32 * 128; i += 256) {
        int r = i >> 7, k4 = i & 127;
        float4 v = ((const float4*)(g_z1 + (size_t)(rb + r) * 512))[k4];
        int k = k4 * 4;
        v.x = v.x * sa[k]     + sb[k];
        v.y = v.y * sa[k + 1] + sb[k + 1];
        v.z = v.z * sa[k + 2] + sb[k + 2];
        v.w = v.w * sa[k + 3] + sb[k + 3];
        v.x = v.x > 0.f ? v.x : 0.1f * v.x;
        v.y = v.y > 0.f ? v.y : 0.1f * v.y;
        v.z = v.z > 0.f ? v.z : 0.1f * v.z;
        v.w = v.w > 0.f ? v.w : 0.1f * v.w;
        ((float4*)(sy + r * 512))[k4] = v;
    }
    __syncthreads();
    int j = jb + (tid & 127);
    int oo = tid >> 7;
    const float4* Wj = (const float4*)(g_W2Tm + (size_t)j * 512);
    float bj = b2[j];
    for (int oi = 0; oi < 2; oi++) {
        int o = oo * 2 + oi;
        float acc[8];
#pragma unroll
        for (int u = 0; u < 8; u++) acc[u] = bj;
#pragma unroll 4
        for (int k4 = 0; k4 < 128; k4++) {
            float4 w = Wj[k4];
#pragma unroll
            for (int u = 0; u < 8; u++) {
                float4 h = ((const float4*)(sy + (o * 8 + u) * 512))[k4];
                acc[u] += w.x * h.x + w.y * h.y + w.z * h.z + w.w * h.w;
            }
        }
#pragma unroll
        for (int u = 0; u < 8; u++)
            g_z2[(size_t)(rb + o * 8 + u) * 256 + j] = acc[u];
    }
}

// ---------------- output: leaky(BN2(z2)) @ W3 + b3 ----------------
__global__ void __launch_bounds__(256) k_out(const float* __restrict__ w3, const float* __restrict__ b3,
                                             float* __restrict__ out) {
    __shared__ float r0[256], r1s[256];
    int b = blockIdx.x, tid = threadIdx.x;
    float v = g_z2[b * 256 + tid] * g_a2[tid] + g_bp2[tid];
    v = v > 0.f ? v : 0.1f * v;
    r0[tid]  = v * w3[tid * 2];
    r1s[tid] = v * w3[tid * 2 + 1];
    __syncthreads();
    for (int s = 128; s > 0; s >>= 1) {
        if (tid < s) { r0[tid] += r0[tid + s]; r1s[tid] += r1s[tid + s]; }
        __syncthreads();
    }
    if (tid == 0) {
        out[b * 2]     = r0[0]  + b3[0];
        out[b * 2 + 1] = r1s[0] + b3[1];
    }
}

// ---------------- launch ----------------
extern "C" void kernel_launch(void* const* d_in, const int* in_sizes, int n_in,
                              void* d_out, int out_size) {
    const int*   uid  = (const int*)d_in[0];
    const int*   mid  = (const int*)d_in[1];
    const int*   cat  = (const int*)d_in[2];
    const int*   hm   = (const int*)d_in[3];
    const int*   hc   = (const int*)d_in[4];
    const int*   mask = (const int*)d_in[5];
    const float* utab = (const float*)d_in[6];
    const float* mtab = (const float*)d_in[7];
    const float* ctab = (const float*)d_in[8];
    const float* lw1  = (const float*)d_in[9];
    const float* lb1  = (const float*)d_in[10];
    const float* lw2  = (const float*)d_in[11];
    const float* lb2  = (const float*)d_in[12];
    const float* lw3  = (const float*)d_in[13];
    const float* lb3  = (const float*)d_in[14];
    const float* bn0g = (const float*)d_in[15];
    const float* bn0b = (const float*)d_in[16];
    const float* mw1  = (const float*)d_in[17];
    const float* mb1  = (const float*)d_in[18];
    const float* bn1g = (const float*)d_in[19];
    const float* bn1b = (const float*)d_in[20];
    const float* mw2  = (const float*)d_in[21];
    const float* mb2  = (const float*)d_in[22];
    const float* bn2g = (const float*)d_in[23];
    const float* bn2b = (const float*)d_in[24];
    const float* mw3  = (const float*)d_in[25];
    const float* mb3  = (const float*)d_in[26];
    float* out = (float*)d_out;

    const int SMEMF = (32 * 448 + 448 * 2) * 4;
    const int SMEMH = (32 * 512 + 512 * 2) * 4;

    cudaFuncSetAttribute(k_lau_mma, cudaFuncAttributeMaxDynamicSharedMemorySize, SMEM_G);
    cudaFuncSetAttribute(k_mlp1,  cudaFuncAttributeMaxDynamicSharedMemorySize, SMEMF);
    cudaFuncSetAttribute(k_mlp2,  cudaFuncAttributeMaxDynamicSharedMemorySize, SMEMH);

    k_prep<<<480, 256>>>(lw1, lw2, mw1, mw2);
    k_curcb<<<BB, 256>>>(mid, cat, mtab, ctab, lb1);
    k_lau_mma<<<BB, NTL, SMEM_G>>>(hm, hc, mtab, ctab, lb2, lw3, lb3);
    k_softlau<<<BB, 256>>>(mask, uid, utab);
    k_bnstats<<<14, 256>>>(0, bn0g, bn0b);
    k_mlp1<<<dim3(32, 4), 256, SMEMF>>>(mb1);
    k_bnstats<<<16, 256>>>(1, bn1g, bn1b);
    k_mlp2<<<dim3(32, 2), 256, SMEMH>>>(mb2);
    k_bnstats<<<8, 256>>>(2, bn2g, bn2b);
    k_out<<<BB, 256>>>(mw3, mb3, out);
}

// round 13
// speedup vs baseline: 1.2238x; 1.2238x over previous
#include <cuda_runtime.h>
#include <cuda_bf16.h>
#include <cstdint>

#define BB 1024
#define TT 200

// ---------------- scratch (device globals; no allocation allowed) ----------------
__device__ float g_WhistT[256 * 128];   // [j][k] : (W1b - W1c)^T
__device__ float g_WmulT [256 * 128];   // [j][k] : W1d^T
__device__ float g_Wcur  [128 * 256];   // [k][j] : W1a + W1c
__device__ __align__(16) __nv_bfloat16 g_W2Tb[128 * 256]; // [j2][k] bf16 lau_w2^T (row-major)
__device__ float g_W1Tm  [512 * 448];   // [j][k] : mlp_w1^T
__device__ float g_W2Tm  [256 * 512];   // [j][k] : mlp_w2^T
__device__ float g_cur[BB * 128];
__device__ float g_cb [BB * 256];
__device__ float g_hist[(size_t)BB * TT * 128];
__device__ float g_aw [BB * TT];
__device__ float g_x  [BB * 448];
__device__ float g_z1 [BB * 512];
__device__ float g_z2 [BB * 256];
__device__ float g_a0[448], g_bp0[448];
__device__ float g_a1[512], g_bp1[512];
__device__ float g_a2[256], g_bp2[256];

// ---------------- warp-MMA helpers (sm_80-era PTX, legal on compute_103) ----------------
__device__ __forceinline__ uint32_t smem_u32(const void* p) {
    uint32_t a;
    asm("{ .reg .u64 t; cvta.to.shared.u64 t, %1; cvt.u32.u64 %0, t; }" : "=r"(a) : "l"(p));
    return a;
}
__device__ __forceinline__ void mma_bf16(float* c, const uint32_t* a, const uint32_t* b) {
    asm volatile("mma.sync.aligned.m16n8k16.row.col.f32.bf16.bf16.f32 "
        "{%0,%1,%2,%3}, {%4,%5,%6,%7}, {%8,%9}, {%0,%1,%2,%3};"
        : "+f"(c[0]), "+f"(c[1]), "+f"(c[2]), "+f"(c[3])
        : "r"(a[0]), "r"(a[1]), "r"(a[2]), "r"(a[3]), "r"(b[0]), "r"(b[1]));
}
__device__ __forceinline__ void ldsm4(uint32_t* r, uint32_t addr) {
    asm volatile("ldmatrix.sync.aligned.m8n8.x4.shared.b16 {%0,%1,%2,%3}, [%4];"
        : "=r"(r[0]), "=r"(r[1]), "=r"(r[2]), "=r"(r[3]) : "r"(addr));
}

// ---------------- prep: fold & transpose weights ----------------
__global__ void k_prep(const float* __restrict__ w1, const float* __restrict__ w2,
                       const float* __restrict__ mw1, const float* __restrict__ mw2) {
    int idx0 = blockIdx.x * blockDim.x + threadIdx.x;
    int stride = gridDim.x * blockDim.x;
    for (int i = idx0; i < 256 * 128; i += stride) {
        int j = i >> 7, k = i & 127;
        g_WhistT[i] = w1[(128 + k) * 256 + j] - w1[(256 + k) * 256 + j];
        g_WmulT[i]  = w1[(384 + k) * 256 + j];
    }
    for (int i = idx0; i < 128 * 256; i += stride) {
        int k = i >> 8, j = i & 255;
        g_Wcur[i] = w1[k * 256 + j] + w1[(256 + k) * 256 + j];
    }
    for (int i = idx0; i < 128 * 256; i += stride) {
        int j2 = i >> 8, k = i & 255;
        g_W2Tb[j2 * 256 + k] = __float2bfloat16_rn(w2[k * 128 + j2]);
    }
    for (int i = idx0; i < 512 * 448; i += stride) {
        int j = i / 448, k = i - j * 448;
        g_W1Tm[i] = mw1[k * 512 + j];
    }
    for (int i = idx0; i < 256 * 512; i += stride) {
        int j = i >> 9, k = i & 511;
        g_W2Tm[i] = mw2[k * 256 + j];
    }
}

// ---------------- cur gather + per-batch folded bias cb ----------------
__global__ void __launch_bounds__(256) k_curcb(const int* __restrict__ mid, const int* __restrict__ cat,
                                               const float* __restrict__ mtab, const float* __restrict__ ctab,
                                               const float* __restrict__ b1) {
    __shared__ float sc[128];
    int b = blockIdx.x, tid = threadIdx.x;
    if (tid < 128) {
        float v = (tid < 64) ? mtab[(size_t)mid[b] * 64 + tid]
                             : ctab[(size_t)cat[b] * 64 + (tid - 64)];
        sc[tid] = v;
        g_cur[b * 128 + tid] = v;
    }
    __syncthreads();
    float acc = b1[tid];
#pragma unroll 8
    for (int k = 0; k < 128; k++) acc += sc[k] * g_Wcur[k * 256 + tid];
    g_cb[b * 256 + tid] = acc;
}

// ---------------- fused LAU via warp MMA (HMMA), 13 warps = 1 m-tile each ----------------
// smem: sA  hist bf16 [208 rows][stride 136 bf16 = 272B]         @ 0      (56,576)
//       sB  Weff^T bf16 [256 rows j][stride 136]                 @ 56576  (69,632)
//       sW2 lau_w2^T bf16 [128 rows j2][stride 264 bf16 = 528B]  @ 126208 (67,584)
//       misc fp32: cb[256] b2[128]@256 w3[128]@384 b3@512 cur[128]@528 @ 193792
#define SM_A    0
#define SM_B    56576
#define SM_W2   126208
#define SM_MISC 193792
#define SMEM_G  196416
#define NTL 416

__global__ void __launch_bounds__(NTL)
k_lau_mma(const int* __restrict__ hm, const int* __restrict__ hc,
          const float* __restrict__ mtab, const float* __restrict__ ctab,
          const float* __restrict__ b2p, const float* __restrict__ w3p,
          const float* __restrict__ b3p) {
    extern __shared__ char smc[];
    uint32_t sb = smem_u32(smc);
    int b = blockIdx.x, tid = threadIdx.x;
    int wid = tid >> 5, lane = tid & 31;
    float* misc = (float*)(smc + SM_MISC);

    // phase 0: misc
    for (int i = tid; i < 256; i += NTL) misc[i] = g_cb[b * 256 + i];
    if (tid < 128) {
        misc[256 + tid] = b2p[tid];
        misc[384 + tid] = w3p[tid];
        misc[528 + tid] = g_cur[b * 128 + tid];
    }
    if (tid == 0) misc[512] = b3p[0];
    __syncthreads();

    // sW2 copy (u32 pairs)
    {
        const uint32_t* src = (const uint32_t*)g_W2Tb;
        for (int i = tid; i < 128 * 128; i += NTL) {
            int j2 = i >> 7, kp = i & 127;
            *(uint32_t*)(smc + SM_W2 + j2 * 528 + kp * 4) = src[i];
        }
    }
    // sB: Weff^T[j][k] = WhistT + cur[k]*WmulT, bf16
    for (int i = tid; i < 256 * 64; i += NTL) {
        int j = i >> 6, kp = i & 63, k = kp * 2;
        float c0 = misc[528 + k], c1 = misc[528 + k + 1];
        float v0 = g_WhistT[j * 128 + k]     + c0 * g_WmulT[j * 128 + k];
        float v1 = g_WhistT[j * 128 + k + 1] + c1 * g_WmulT[j * 128 + k + 1];
        __nv_bfloat162 p = __floats2bfloat162_rn(v0, v1);
        *(uint32_t*)(smc + SM_B + j * 272 + kp * 4) = *(uint32_t*)&p;
    }
    // hist gather: fp32 -> g_hist, bf16 -> sA
    const int* hmb = hm + b * TT;
    const int* hcb = hc + b * TT;
    for (int i = tid; i < TT * 32; i += NTL) {
        int t = i >> 5, c4 = i & 31;
        float4 v = (c4 < 16) ? ((const float4*)(mtab + (size_t)hmb[t] * 64))[c4]
                             : ((const float4*)(ctab + (size_t)hcb[t] * 64))[c4 - 16];
        ((float4*)(g_hist + ((size_t)b * TT + t) * 128))[c4] = v;
        __nv_bfloat162 p0 = __floats2bfloat162_rn(v.x, v.y);
        __nv_bfloat162 p1 = __floats2bfloat162_rn(v.z, v.w);
        uint2 u; u.x = *(uint32_t*)&p0; u.y = *(uint32_t*)&p1;
        *(uint2*)(smc + SM_A + t * 272 + c4 * 8) = u;
    }
    // zero pad rows 200..207
    for (int i = tid; i < 136; i += NTL)
        ((uint4*)(smc + SM_A + 200 * 272))[i] = make_uint4(0, 0, 0, 0);
    __syncthreads();

    // per-lane ldmatrix base addresses
    uint32_t aBase  = sb + SM_A  + (lane & 7) * 272 + ((lane >> 3) & 1) * (8 * 272) + ((lane >> 4) & 1) * 16;
    uint32_t bBase4 = sb + SM_B  + (lane & 7) * 272 + ((lane >> 3) & 1) * 16 + ((lane >> 4) & 1) * (8 * 272);
    uint32_t wBase4 = sb + SM_W2 + (lane & 7) * 528 + ((lane >> 3) & 1) * 16 + ((lane >> 4) & 1) * (8 * 528);

    int mt = wid;  // 13 warps, 13 m-tiles
    float acc2[16][4];
#pragma unroll
    for (int i = 0; i < 16; i++)
        acc2[i][0] = acc2[i][1] = acc2[i][2] = acc2[i][3] = 0.f;
    uint32_t aRow = aBase + mt * (16 * 272);

#pragma unroll
    for (int h = 0; h < 2; h++) {
#pragma unroll
        for (int q = 0; q < 2; q++) {
            // GEMM1 quarter: N cols [h*128+q*64, +64), K=128
            float acc1[8][4];
#pragma unroll
            for (int i = 0; i < 8; i++)
                acc1[i][0] = acc1[i][1] = acc1[i][2] = acc1[i][3] = 0.f;
            uint32_t bQ = bBase4 + (h * 128 + q * 64) * 272;
#pragma unroll
            for (int k0 = 0; k0 < 128; k0 += 16) {
                uint32_t a[4]; ldsm4(a, aRow + k0 * 2);
#pragma unroll
                for (int p = 0; p < 4; p++) {
                    uint32_t bf[4];
                    ldsm4(bf, bQ + p * (16 * 272) + k0 * 2);
                    mma_bf16(acc1[2 * p],     a, bf);
                    mma_bf16(acc1[2 * p + 1], a, bf + 2);
                }
            }
            // sigmoid + pack to A-fragments for GEMM2 (fragment layouts coincide)
            uint32_t hb[16];
#pragma unroll
            for (int ns = 0; ns < 8; ns++) {
                int n = h * 128 + q * 64 + ns * 8 + (lane & 3) * 2;
                float cb0 = misc[n], cb1 = misc[n + 1];
                float s0 = 1.f / (1.f + __expf(-(acc1[ns][0] + cb0)));
                float s1 = 1.f / (1.f + __expf(-(acc1[ns][1] + cb1)));
                float s2 = 1.f / (1.f + __expf(-(acc1[ns][2] + cb0)));
                float s3 = 1.f / (1.f + __expf(-(acc1[ns][3] + cb1)));
                __nv_bfloat162 p0 = __floats2bfloat162_rn(s0, s1);
                __nv_bfloat162 p1 = __floats2bfloat162_rn(s2, s3);
                hb[ns * 2]     = *(uint32_t*)&p0;
                hb[ns * 2 + 1] = *(uint32_t*)&p1;
            }
            // GEMM2 partial: K cols [h*128+q*64, +64) of W2^T, N=128
#pragma unroll
            for (int ktl = 0; ktl < 4; ktl++) {
                int kt = h * 8 + q * 4 + ktl;
                const uint32_t* a2 = &hb[ktl * 4];
#pragma unroll
                for (int p2 = 0; p2 < 8; p2++) {
                    uint32_t bf[4];
                    ldsm4(bf, wBase4 + p2 * (16 * 528) + kt * 32);
                    mma_bf16(acc2[2 * p2],     a2, bf);
                    mma_bf16(acc2[2 * p2 + 1], a2, bf + 2);
                }
            }
        }
    }
    // epilogue: aw[t] = sum_j sigmoid(h2 + b2)*w3 + b3
    float pa = 0.f, pb = 0.f;
#pragma unroll
    for (int ns2 = 0; ns2 < 16; ns2++) {
        int n = ns2 * 8 + (lane & 3) * 2;
        float b20 = misc[256 + n], b21 = misc[256 + n + 1];
        float w30 = misc[384 + n], w31 = misc[384 + n + 1];
        pa += w30 / (1.f + __expf(-(acc2[ns2][0] + b20)));
        pa += w31 / (1.f + __expf(-(acc2[ns2][1] + b21)));
        pb += w30 / (1.f + __expf(-(acc2[ns2][2] + b20)));
        pb += w31 / (1.f + __expf(-(acc2[ns2][3] + b21)));
    }
    pa += __shfl_xor_sync(0xffffffffu, pa, 1);
    pa += __shfl_xor_sync(0xffffffffu, pa, 2);
    pb += __shfl_xor_sync(0xffffffffu, pb, 1);
    pb += __shfl_xor_sync(0xffffffffu, pb, 2);
    if ((lane & 3) == 0) {
        int t = mt * 16 + (lane >> 2);
        float b3v = misc[512];
        if (t < TT)     g_aw[b * TT + t]     = pa + b3v;
        if (t + 8 < TT) g_aw[b * TT + t + 8] = pb + b3v;
    }
}

// ---------------- softmax + lau + hmean + assemble x ----------------
__global__ void __launch_bounds__(256) k_softlau(const int* __restrict__ mask, const int* __restrict__ uid,
                                                 const float* __restrict__ utab) {
    __shared__ float ssc[200], smf[200], red[256];
    __shared__ float c1[128], c2[128];
    __shared__ float s_mx, s_sum, s_nm;
    int b = blockIdx.x, tid = threadIdx.x;
    float a = -1e30f, mf = 0.f;
    if (tid < 200) {
        int m = mask[b * TT + tid];
        mf = (float)m;
        float v = g_aw[b * TT + tid];
        a = m ? v : -1e30f;
        smf[tid] = mf;
    }
    red[tid] = a; __syncthreads();
    for (int s = 128; s > 0; s >>= 1) { if (tid < s) red[tid] = fmaxf(red[tid], red[tid + s]); __syncthreads(); }
    if (tid == 0) s_mx = red[0];
    __syncthreads();
    float e = (tid < 200 && mf > 0.f) ? __expf(a - s_mx) : 0.f;
    red[tid] = e; __syncthreads();
    for (int s = 128; s > 0; s >>= 1) { if (tid < s) red[tid] += red[tid + s]; __syncthreads(); }
    if (tid == 0) s_sum = red[0];
    __syncthreads();
    red[tid] = mf; __syncthreads();
    for (int s = 128; s > 0; s >>= 1) { if (tid < s) red[tid] += red[tid + s]; __syncthreads(); }
    if (tid == 0) s_nm = red[0];
    __syncthreads();
    if (tid < 200) ssc[tid] = e / s_sum;
    __syncthreads();

    int j = tid & 127, half = tid >> 7;
    float accL = 0.f, accM = 0.f;
    int t0 = half * 100;
    for (int t = t0; t < t0 + 100; t++) {
        float h = g_hist[((size_t)b * TT + t) * 128 + j];
        accL += ssc[t] * h;
        accM += smf[t] * h;
    }
    if (half == 1) { c1[j] = accL; c2[j] = accM; }
    __syncthreads();
    if (tid < 64) g_x[b * 448 + tid] = utab[(size_t)uid[b] * 64 + tid];
    if (half == 0) {
        g_x[b * 448 + 64 + j]  = g_cur[b * 128 + j];
        g_x[b * 448 + 192 + j] = accL + c1[j];
        g_x[b * 448 + 320 + j] = (accM + c2[j]) / s_nm;
    }
}

// ---------------- batch-norm stats, coalesced: 32 features/block ----------------
__global__ void __launch_bounds__(256) k_bnstats(int which, const float* __restrict__ gamma,
                                                 const float* __restrict__ beta) {
    const float* src; float* a; float* bp; int F;
    if (which == 0)      { src = g_x;  a = g_a0; bp = g_bp0; F = 448; }
    else if (which == 1) { src = g_z1; a = g_a1; bp = g_bp1; F = 512; }
    else                 { src = g_z2; a = g_a2; bp = g_bp2; F = 256; }
    __shared__ float sh1[8][33], sh2[8][33];
    int tid = threadIdx.x;
    int fl = tid & 31, rg = tid >> 5;            // 8 row-groups
    int f = blockIdx.x * 32 + fl;
    float s = 0.f, s2 = 0.f;
    for (int r = rg; r < BB; r += 8) {
        float v = src[(size_t)r * F + f];
        s += v; s2 += v * v;
    }
    sh1[rg][fl] = s; sh2[rg][fl] = s2;
    __syncthreads();
    if (rg == 0) {
#pragma unroll
        for (int i = 1; i < 8; i++) { s += sh1[i][fl]; s2 += sh2[i][fl]; }
        float mean = s * (1.f / BB);
        float var = s2 * (1.f / BB) - mean * mean;
        float ai = gamma[f] * rsqrtf(var + 1e-5f);
        a[f] = ai;
        bp[f] = beta[f] - mean * ai;
    }
}

// ---------------- MLP layer 1: z1 = BN0(x) @ W1 + b1  (grid 32 x 4) ----------------
__global__ void __launch_bounds__(256) k_mlp1(const float* __restrict__ b1) {
    extern __shared__ float sm[];
    float* sx = sm;                // 32*448
    float* sa = sx + 32 * 448;     // 448
    float* sb = sa + 448;          // 448
    int rb = blockIdx.x * 32, jb = blockIdx.y * 128, tid = threadIdx.x;
    for (int i = tid; i < 448; i += 256) { sa[i] = g_a0[i]; sb[i] = g_bp0[i]; }
    __syncthreads();
    for (int i = tid; i < 32 * 112; i += 256) {
        int r = i / 112, k4 = i - r * 112;
        float4 v = ((const float4*)(g_x + (size_t)(rb + r) * 448))[k4];
        int k = k4 * 4;
        v.x = v.x * sa[k]     + sb[k];
        v.y = v.y * sa[k + 1] + sb[k + 1];
        v.z = v.z * sa[k + 2] + sb[k + 2];
        v.w = v.w * sa[k + 3] + sb[k + 3];
        ((float4*)(sx + r * 448))[k4] = v;
    }
    __syncthreads();
    int j = jb + (tid & 127);
    int oo = tid >> 7;
    const float4* Wj = (const float4*)(g_W1Tm + (size_t)j * 448);
    float bj = b1[j];
    for (int oi = 0; oi < 2; oi++) {
        int o = oo * 2 + oi;
        float acc[8];
#pragma unroll
        for (int u = 0; u < 8; u++) acc[u] = bj;
#pragma unroll 4
        for (int k4 = 0; k4 < 112; k4++) {
            float4 w = Wj[k4];
#pragma unroll
            for (int u = 0; u < 8; u++) {
                float4 h = ((const float4*)(sx + (o * 8 + u) * 448))[k4];
                acc[u] += w.x * h.x + w.y * h.y + w.z * h.z + w.w * h.w;
            }
        }
#pragma unroll
        for (int u = 0; u < 8; u++)
            g_z1[(size_t)(rb + o * 8 + u) * 512 + j] = acc[u];
    }
}

// ---------------- MLP layer 2: z2 = leaky(BN1(z1)) @ W2 + b2  (grid 32 x 2) ----------------
__global__ void __launch_bounds__(256) k_mlp2(const float* __restrict__ b2) {
    extern __shared__ float sm[];
    float* sy = sm;                // 32*512
    float* sa = sy + 32 * 512;     // 512
    float* sb = sa + 512;          // 512
    int rb = blockIdx.x * 32, jb = blockIdx.y * 128, tid = threadIdx.x;
    for (int i = tid; i < 512; i += 256) { sa[i] = g_a1[i]; sb[i] = g_bp1[i]; }
    __syncthreads();
    for (int i = tid; i < 32 * 128; i += 256) {
        int r = i >> 7, k4 = i & 127;
        float4 v = ((const float4*)(g_z1 + (size_t)(rb + r) * 512))[k4];
        int k = k4 * 4;
        v.x = v.x * sa[k]     + sb[k];
        v.y = v.y * sa[k + 1] + sb[k + 1];
        v.z = v.z * sa[k + 2] + sb[k + 2];
        v.w = v.w * sa[k + 3] + sb[k + 3];
        v.x = v.x > 0.f ? v.x : 0.1f * v.x;
        v.y = v.y > 0.f ? v.y : 0.1f * v.y;
        v.z = v.z > 0.f ? v.z : 0.1f * v.z;
        v.w = v.w > 0.f ? v.w : 0.1f * v.w;
        ((float4*)(sy + r * 512))[k4] = v;
    }
    __syncthreads();
    int j = jb + (tid & 127);
    int oo = tid >> 7;
    const float4* Wj = (const float4*)(g_W2Tm + (size_t)j * 512);
    float bj = b2[j];
    for (int oi = 0; oi < 2; oi++) {
        int o = oo * 2 + oi;
        float acc[8];
#pragma unroll
        for (int u = 0; u < 8; u++) acc[u] = bj;
#pragma unroll 4
        for (int k4 = 0; k4 < 128; k4++) {
            float4 w = Wj[k4];
#pragma unroll
            for (int u = 0; u < 8; u++) {
                float4 h = ((const float4*)(sy + (o * 8 + u) * 512))[k4];
                acc[u] += w.x * h.x + w.y * h.y + w.z * h.z + w.w * h.w;
            }
        }
#pragma unroll
        for (int u = 0; u < 8; u++)
            g_z2[(size_t)(rb + o * 8 + u) * 256 + j] = acc[u];
    }
}

// ---------------- output: leaky(BN2(z2)) @ W3 + b3 ----------------
__global__ void __launch_bounds__(256) k_out(const float* __restrict__ w3, const float* __restrict__ b3,
                                             float* __restrict__ out) {
    __shared__ float r0[256], r1s[256];
    int b = blockIdx.x, tid = threadIdx.x;
    float v = g_z2[b * 256 + tid] * g_a2[tid] + g_bp2[tid];
    v = v > 0.f ? v : 0.1f * v;
    r0[tid]  = v * w3[tid * 2];
    r1s[tid] = v * w3[tid * 2 + 1];
    __syncthreads();
    for (int s = 128; s > 0; s >>= 1) {
        if (tid < s) { r0[tid] += r0[tid + s]; r1s[tid] += r1s[tid + s]; }
        __syncthreads();
    }
    if (tid == 0) {
        out[b * 2]     = r0[0]  + b3[0];
        out[b * 2 + 1] = r1s[0] + b3[1];
    }
}

// ---------------- launch ----------------
extern "C" void kernel_launch(void* const* d_in, const int* in_sizes, int n_in,
                              void* d_out, int out_size) {
    const int*   uid  = (const int*)d_in[0];
    const int*   mid  = (const int*)d_in[1];
    const int*   cat  = (const int*)d_in[2];
    const int*   hm   = (const int*)d_in[3];
    const int*   hc   = (const int*)d_in[4];
    const int*   mask = (const int*)d_in[5];
    const float* utab = (const float*)d_in[6];
    const float* mtab = (const float*)d_in[7];
    const float* ctab = (const float*)d_in[8];
    const float* lw1  = (const float*)d_in[9];
    const float* lb1  = (const float*)d_in[10];
    const float* lw2  = (const float*)d_in[11];
    const float* lb2  = (const float*)d_in[12];
    const float* lw3  = (const float*)d_in[13];
    const float* lb3  = (const float*)d_in[14];
    const float* bn0g = (const float*)d_in[15];
    const float* bn0b = (const float*)d_in[16];
    const float* mw1  = (const float*)d_in[17];
    const float* mb1  = (const float*)d_in[18];
    const float* bn1g = (const float*)d_in[19];
    const float* bn1b = (const float*)d_in[20];
    const float* mw2  = (const float*)d_in[21];
    const float* mb2  = (const float*)d_in[22];
    const float* bn2g = (const float*)d_in[23];
    const float* bn2b = (const float*)d_in[24];
    const float* mw3  = (const float*)d_in[25];
    const float* mb3  = (const float*)d_in[26];
    float* out = (float*)d_out;

    const int SMEMF = (32 * 448 + 448 * 2) * 4;
    const int SMEMH = (32 * 512 + 512 * 2) * 4;

    cudaFuncSetAttribute(k_lau_mma, cudaFuncAttributeMaxDynamicSharedMemorySize, SMEM_G);
    cudaFuncSetAttribute(k_mlp1,  cudaFuncAttributeMaxDynamicSharedMemorySize, SMEMF);
    cudaFuncSetAttribute(k_mlp2,  cudaFuncAttributeMaxDynamicSharedMemorySize, SMEMH);

    k_prep<<<480, 256>>>(lw1, lw2, mw1, mw2);
    k_curcb<<<BB, 256>>>(mid, cat, mtab, ctab, lb1);
    k_lau_mma<<<BB, NTL, SMEM_G>>>(hm, hc, mtab, ctab, lb2, lw3, lb3);
    k_softlau<<<BB, 256>>>(mask, uid, utab);
    k_bnstats<<<14, 256>>>(0, bn0g, bn0b);
    k_mlp1<<<dim3(32, 4), 256, SMEMF>>>(mb1);
    k_bnstats<<<16, 256>>>(1, bn1g, bn1b);
    k_mlp2<<<dim3(32, 2), 256, SMEMH>>>(mb2);
    k_bnstats<<<8, 256>>>(2, bn2g, bn2b);
    k_out<<<BB, 256>>>(mw3, mb3, out);
}

// round 17
// speedup vs baseline: 1.4633x; 1.1957x over previous
#include <cuda_runtime.h>
#include <cuda_bf16.h>
#include <cstdint>

#define BB 1024
#define TT 200

// ---------------- scratch (device globals; no allocation allowed) ----------------
__device__ uint32_t g_WhT2[256 * 64];   // [j][k/2] : bf16x2 (W1b - W1c)^T
__device__ uint32_t g_WmT2[256 * 64];   // [j][k/2] : bf16x2 W1d^T
__device__ float g_Wcur  [128 * 256];   // [k][j] : W1a + W1c
__device__ __align__(16) __nv_bfloat16 g_W2Tb[128 * 256]; // [j2][k] bf16 lau_w2^T (row-major)
__device__ float g_W1Tm  [512 * 448];   // [j][k] : mlp_w1^T
__device__ float g_W2Tm  [256 * 512];   // [j][k] : mlp_w2^T
__device__ float g_cur[BB * 128];
__device__ float g_cb [BB * 256];
__device__ float g_hist[(size_t)BB * TT * 128];
__device__ float g_aw [BB * TT];
__device__ float g_x  [BB * 448];
__device__ float g_z1 [BB * 512];
__device__ float g_z2 [BB * 256];
__device__ float g_a0[448], g_bp0[448];
__device__ float g_a1[512], g_bp1[512];
__device__ float g_a2[256], g_bp2[256];

// ---------------- warp-MMA helpers (sm_80-era PTX, legal on compute_103) ----------------
__device__ __forceinline__ uint32_t smem_u32(const void* p) {
    uint32_t a;
    asm("{ .reg .u64 t; cvta.to.shared.u64 t, %1; cvt.u32.u64 %0, t; }" : "=r"(a) : "l"(p));
    return a;
}
__device__ __forceinline__ void mma_bf16(float* c, const uint32_t* a, const uint32_t* b) {
    asm volatile("mma.sync.aligned.m16n8k16.row.col.f32.bf16.bf16.f32 "
        "{%0,%1,%2,%3}, {%4,%5,%6,%7}, {%8,%9}, {%0,%1,%2,%3};"
        : "+f"(c[0]), "+f"(c[1]), "+f"(c[2]), "+f"(c[3])
        : "r"(a[0]), "r"(a[1]), "r"(a[2]), "r"(a[3]), "r"(b[0]), "r"(b[1]));
}
__device__ __forceinline__ void ldsm4(uint32_t* r, uint32_t addr) {
    asm volatile("ldmatrix.sync.aligned.m8n8.x4.shared.b16 {%0,%1,%2,%3}, [%4];"
        : "=r"(r[0]), "=r"(r[1]), "=r"(r[2]), "=r"(r[3]) : "r"(addr));
}
// sigmoid(x) = 0.5*tanh(x/2)+0.5 : 1 MUFU (tanh.approx) + FMAs instead of EX2+RCP/div
__device__ __forceinline__ float sigmoid_t(float x) {
    float t;
    asm("tanh.approx.f32 %0, %1;" : "=f"(t) : "f"(x * 0.5f));
    return fmaf(t, 0.5f, 0.5f);
}

// ---------------- prep: fold & transpose weights ----------------
__global__ void k_prep(const float* __restrict__ w1, const float* __restrict__ w2,
                       const float* __restrict__ mw1, const float* __restrict__ mw2) {
    int idx0 = blockIdx.x * blockDim.x + threadIdx.x;
    int stride = gridDim.x * blockDim.x;
    for (int i = idx0; i < 256 * 64; i += stride) {
        int j = i >> 6, k = (i & 63) * 2;
        float h0 = w1[(128 + k) * 256 + j]     - w1[(256 + k) * 256 + j];
        float h1 = w1[(128 + k + 1) * 256 + j] - w1[(256 + k + 1) * 256 + j];
        float m0 = w1[(384 + k) * 256 + j];
        float m1 = w1[(384 + k + 1) * 256 + j];
        __nv_bfloat162 ph = __floats2bfloat162_rn(h0, h1);
        __nv_bfloat162 pm = __floats2bfloat162_rn(m0, m1);
        g_WhT2[i] = *(uint32_t*)&ph;
        g_WmT2[i] = *(uint32_t*)&pm;
    }
    for (int i = idx0; i < 128 * 256; i += stride) {
        int k = i >> 8, j = i & 255;
        g_Wcur[i] = w1[k * 256 + j] + w1[(256 + k) * 256 + j];
    }
    for (int i = idx0; i < 128 * 256; i += stride) {
        int j2 = i >> 8, k = i & 255;
        g_W2Tb[j2 * 256 + k] = __float2bfloat16_rn(w2[k * 128 + j2]);
    }
    for (int i = idx0; i < 512 * 448; i += stride) {
        int j = i / 448, k = i - j * 448;
        g_W1Tm[i] = mw1[k * 512 + j];
    }
    for (int i = idx0; i < 256 * 512; i += stride) {
        int j = i >> 9, k = i & 511;
        g_W2Tm[i] = mw2[k * 256 + j];
    }
}

// ---------------- cur gather + per-batch folded bias cb ----------------
__global__ void __launch_bounds__(256) k_curcb(const int* __restrict__ mid, const int* __restrict__ cat,
                                               const float* __restrict__ mtab, const float* __restrict__ ctab,
                                               const float* __restrict__ b1) {
    __shared__ float sc[128];
    int b = blockIdx.x, tid = threadIdx.x;
    if (tid < 128) {
        float v = (tid < 64) ? mtab[(size_t)mid[b] * 64 + tid]
                             : ctab[(size_t)cat[b] * 64 + (tid - 64)];
        sc[tid] = v;
        g_cur[b * 128 + tid] = v;
    }
    __syncthreads();
    float acc = b1[tid];
#pragma unroll 8
    for (int k = 0; k < 128; k++) acc += sc[k] * g_Wcur[k * 256 + tid];
    g_cb[b * 256 + tid] = acc;
}

// ---------------- fused LAU via warp MMA (HMMA), 13 warps = 1 m-tile each ----------------
// smem: sA  hist bf16 [208 rows][stride 136 bf16 = 272B]         @ 0      (56,576)
//       sB  Weff^T bf16 [256 rows j][stride 136]                 @ 56576  (69,632)
//       sW2 lau_w2^T bf16 [128 rows j2][stride 264 bf16 = 528B]  @ 126208 (67,584)
//       misc fp32: cb[256] b2[128]@256 w3[128]@384 b3@512 cur[128]@528 @ 193792
#define SM_A    0
#define SM_B    56576
#define SM_W2   126208
#define SM_MISC 193792
#define SMEM_G  196416
#define NTL 416

__global__ void __launch_bounds__(NTL)
k_lau_mma(const int* __restrict__ hm, const int* __restrict__ hc,
          const float* __restrict__ mtab, const float* __restrict__ ctab,
          const float* __restrict__ b2p, const float* __restrict__ w3p,
          const float* __restrict__ b3p) {
    extern __shared__ char smc[];
    uint32_t sb = smem_u32(smc);
    int b = blockIdx.x, tid = threadIdx.x;
    int wid = tid >> 5, lane = tid & 31;
    float* misc = (float*)(smc + SM_MISC);

    // phase 0: misc
    for (int i = tid; i < 256; i += NTL) misc[i] = g_cb[b * 256 + i];
    if (tid < 128) {
        misc[256 + tid] = b2p[tid];
        misc[384 + tid] = w3p[tid];
        misc[528 + tid] = g_cur[b * 128 + tid];
    }
    if (tid == 0) misc[512] = b3p[0];
    __syncthreads();

    // sW2 copy (u32 pairs)
    {
        const uint32_t* src = (const uint32_t*)g_W2Tb;
        for (int i = tid; i < 128 * 128; i += NTL) {
            int j2 = i >> 7, kp = i & 127;
            *(uint32_t*)(smc + SM_W2 + j2 * 528 + kp * 4) = src[i];
        }
    }
    // sB: Weff^T[j][k] = WhistT + cur[k]*WmulT, from bf16-packed tables
    for (int i = tid; i < 256 * 64; i += NTL) {
        int j = i >> 6, kp = i & 63, k = kp * 2;
        float c0 = misc[528 + k], c1 = misc[528 + k + 1];
        uint32_t uh = g_WhT2[i], um = g_WmT2[i];
        float2 wh = __bfloat1622float2(*(__nv_bfloat162*)&uh);
        float2 wm = __bfloat1622float2(*(__nv_bfloat162*)&um);
        float v0 = fmaf(c0, wm.x, wh.x);
        float v1 = fmaf(c1, wm.y, wh.y);
        __nv_bfloat162 p = __floats2bfloat162_rn(v0, v1);
        *(uint32_t*)(smc + SM_B + j * 272 + kp * 4) = *(uint32_t*)&p;
    }
    // hist gather: fp32 -> g_hist, bf16 -> sA
    const int* hmb = hm + b * TT;
    const int* hcb = hc + b * TT;
    for (int i = tid; i < TT * 32; i += NTL) {
        int t = i >> 5, c4 = i & 31;
        float4 v = (c4 < 16) ? ((const float4*)(mtab + (size_t)hmb[t] * 64))[c4]
                             : ((const float4*)(ctab + (size_t)hcb[t] * 64))[c4 - 16];
        ((float4*)(g_hist + ((size_t)b * TT + t) * 128))[c4] = v;
        __nv_bfloat162 p0 = __floats2bfloat162_rn(v.x, v.y);
        __nv_bfloat162 p1 = __floats2bfloat162_rn(v.z, v.w);
        uint2 u; u.x = *(uint32_t*)&p0; u.y = *(uint32_t*)&p1;
        *(uint2*)(smc + SM_A + t * 272 + c4 * 8) = u;
    }
    // zero pad rows 200..207
    for (int i = tid; i < 136; i += NTL)
        ((uint4*)(smc + SM_A + 200 * 272))[i] = make_uint4(0, 0, 0, 0);
    __syncthreads();

    // per-lane ldmatrix base addresses
    uint32_t aBase  = sb + SM_A  + (lane & 7) * 272 + ((lane >> 3) & 1) * (8 * 272) + ((lane >> 4) & 1) * 16;
    uint32_t bBase4 = sb + SM_B  + (lane & 7) * 272 + ((lane >> 3) & 1) * 16 + ((lane >> 4) & 1) * (8 * 272);
    uint32_t wBase4 = sb + SM_W2 + (lane & 7) * 528 + ((lane >> 3) & 1) * 16 + ((lane >> 4) & 1) * (8 * 528);

    int mt = wid;  // 13 warps, 13 m-tiles
    float acc2[16][4];
#pragma unroll
    for (int i = 0; i < 16; i++)
        acc2[i][0] = acc2[i][1] = acc2[i][2] = acc2[i][3] = 0.f;
    uint32_t aRow = aBase + mt * (16 * 272);

#pragma unroll
    for (int h = 0; h < 2; h++) {
#pragma unroll
        for (int q = 0; q < 2; q++) {
            // GEMM1 quarter: N cols [h*128+q*64, +64), K=128
            float acc1[8][4];
#pragma unroll
            for (int i = 0; i < 8; i++)
                acc1[i][0] = acc1[i][1] = acc1[i][2] = acc1[i][3] = 0.f;
            uint32_t bQ = bBase4 + (h * 128 + q * 64) * 272;
#pragma unroll
            for (int k0 = 0; k0 < 128; k0 += 16) {
                uint32_t a[4]; ldsm4(a, aRow + k0 * 2);
#pragma unroll
                for (int p = 0; p < 4; p++) {
                    uint32_t bf[4];
                    ldsm4(bf, bQ + p * (16 * 272) + k0 * 2);
                    mma_bf16(acc1[2 * p],     a, bf);
                    mma_bf16(acc1[2 * p + 1], a, bf + 2);
                }
            }
            // sigmoid + pack to A-fragments for GEMM2 (fragment layouts coincide)
            uint32_t hb[16];
#pragma unroll
            for (int ns = 0; ns < 8; ns++) {
                int n = h * 128 + q * 64 + ns * 8 + (lane & 3) * 2;
                float cb0 = misc[n], cb1 = misc[n + 1];
                float s0 = sigmoid_t(acc1[ns][0] + cb0);
                float s1 = sigmoid_t(acc1[ns][1] + cb1);
                float s2 = sigmoid_t(acc1[ns][2] + cb0);
                float s3 = sigmoid_t(acc1[ns][3] + cb1);
                __nv_bfloat162 p0 = __floats2bfloat162_rn(s0, s1);
                __nv_bfloat162 p1 = __floats2bfloat162_rn(s2, s3);
                hb[ns * 2]     = *(uint32_t*)&p0;
                hb[ns * 2 + 1] = *(uint32_t*)&p1;
            }
            // GEMM2 partial: K cols [h*128+q*64, +64) of W2^T, N=128
#pragma unroll
            for (int ktl = 0; ktl < 4; ktl++) {
                int kt = h * 8 + q * 4 + ktl;
                const uint32_t* a2 = &hb[ktl * 4];
#pragma unroll
                for (int p2 = 0; p2 < 8; p2++) {
                    uint32_t bf[4];
                    ldsm4(bf, wBase4 + p2 * (16 * 528) + kt * 32);
                    mma_bf16(acc2[2 * p2],     a2, bf);
                    mma_bf16(acc2[2 * p2 + 1], a2, bf + 2);
                }
            }
        }
    }
    // epilogue: aw[t] = sum_j sigmoid(h2 + b2)*w3 + b3
    float pa = 0.f, pb = 0.f;
#pragma unroll
    for (int ns2 = 0; ns2 < 16; ns2++) {
        int n = ns2 * 8 + (lane & 3) * 2;
        float b20 = misc[256 + n], b21 = misc[256 + n + 1];
        float w30 = misc[384 + n], w31 = misc[384 + n + 1];
        pa = fmaf(w30, sigmoid_t(acc2[ns2][0] + b20), pa);
        pa = fmaf(w31, sigmoid_t(acc2[ns2][1] + b21), pa);
        pb = fmaf(w30, sigmoid_t(acc2[ns2][2] + b20), pb);
        pb = fmaf(w31, sigmoid_t(acc2[ns2][3] + b21), pb);
    }
    pa += __shfl_xor_sync(0xffffffffu, pa, 1);
    pa += __shfl_xor_sync(0xffffffffu, pa, 2);
    pb += __shfl_xor_sync(0xffffffffu, pb, 1);
    pb += __shfl_xor_sync(0xffffffffu, pb, 2);
    if ((lane & 3) == 0) {
        int t = mt * 16 + (lane >> 2);
        float b3v = misc[512];
        if (t < TT)     g_aw[b * TT + t]     = pa + b3v;
        if (t + 8 < TT) g_aw[b * TT + t + 8] = pb + b3v;
    }
}

// ---------------- softmax + lau + hmean + assemble x ----------------
__global__ void __launch_bounds__(256) k_softlau(const int* __restrict__ mask, const int* __restrict__ uid,
                                                 const float* __restrict__ utab) {
    __shared__ float ssc[200], smf[200], red[256];
    __shared__ float c1[128], c2[128];
    __shared__ float s_mx, s_sum, s_nm;
    int b = blockIdx.x, tid = threadIdx.x;
    float a = -1e30f, mf = 0.f;
    if (tid < 200) {
        int m = mask[b * TT + tid];
        mf = (float)m;
        float v = g_aw[b * TT + tid];
        a = m ? v : -1e30f;
        smf[tid] = mf;
    }
    red[tid] = a; __syncthreads();
    for (int s = 128; s > 0; s >>= 1) { if (tid < s) red[tid] = fmaxf(red[tid], red[tid + s]); __syncthreads(); }
    if (tid == 0) s_mx = red[0];
    __syncthreads();
    float e = (tid < 200 && mf > 0.f) ? __expf(a - s_mx) : 0.f;
    red[tid] = e; __syncthreads();
    for (int s = 128; s > 0; s >>= 1) { if (tid < s) red[tid] += red[tid + s]; __syncthreads(); }
    if (tid == 0) s_sum = red[0];
    __syncthreads();
    red[tid] = mf; __syncthreads();
    for (int s = 128; s > 0; s >>= 1) { if (tid < s) red[tid] += red[tid + s]; __syncthreads(); }
    if (tid == 0) s_nm = red[0];
    __syncthreads();
    if (tid < 200) ssc[tid] = e / s_sum;
    __syncthreads();

    int j = tid & 127, half = tid >> 7;
    float accL = 0.f, accM = 0.f;
    int t0 = half * 100;
    for (int t = t0; t < t0 + 100; t++) {
        float h = g_hist[((size_t)b * TT + t) * 128 + j];
        accL += ssc[t] * h;
        accM += smf[t] * h;
    }
    if (half == 1) { c1[j] = accL; c2[j] = accM; }
    __syncthreads();
    if (tid < 64) g_x[b * 448 + tid] = utab[(size_t)uid[b] * 64 + tid];
    if (half == 0) {
        g_x[b * 448 + 64 + j]  = g_cur[b * 128 + j];
        g_x[b * 448 + 192 + j] = accL + c1[j];
        g_x[b * 448 + 320 + j] = (accM + c2[j]) / s_nm;
    }
}

// ---------------- batch-norm stats, coalesced: 32 features/block ----------------
__global__ void __launch_bounds__(256) k_bnstats(int which, const float* __restrict__ gamma,
                                                 const float* __restrict__ beta) {
    const float* src; float* a; float* bp; int F;
    if (which == 0)      { src = g_x;  a = g_a0; bp = g_bp0; F = 448; }
    else if (which == 1) { src = g_z1; a = g_a1; bp = g_bp1; F = 512; }
    else                 { src = g_z2; a = g_a2; bp = g_bp2; F = 256; }
    __shared__ float sh1[8][33], sh2[8][33];
    int tid = threadIdx.x;
    int fl = tid & 31, rg = tid >> 5;            // 8 row-groups
    int f = blockIdx.x * 32 + fl;
    float s = 0.f, s2 = 0.f;
    for (int r = rg; r < BB; r += 8) {
        float v = src[(size_t)r * F + f];
        s += v; s2 += v * v;
    }
    sh1[rg][fl] = s; sh2[rg][fl] = s2;
    __syncthreads();
    if (rg == 0) {
#pragma unroll
        for (int i = 1; i < 8; i++) { s += sh1[i][fl]; s2 += sh2[i][fl]; }
        float mean = s * (1.f / BB);
        float var = s2 * (1.f / BB) - mean * mean;
        float ai = gamma[f] * rsqrtf(var + 1e-5f);
        a[f] = ai;
        bp[f] = beta[f] - mean * ai;
    }
}

// ---------------- MLP layer 1: z1 = BN0(x) @ W1 + b1  (grid 32 x 4) ----------------
__global__ void __launch_bounds__(256) k_mlp1(const float* __restrict__ b1) {
    extern __shared__ float sm[];
    float* sx = sm;                // 32*448
    float* sa = sx + 32 * 448;     // 448
    float* sb = sa + 448;          // 448
    int rb = blockIdx.x * 32, jb = blockIdx.y * 128, tid = threadIdx.x;
    for (int i = tid; i < 448; i += 256) { sa[i] = g_a0[i]; sb[i] = g_bp0[i]; }
    __syncthreads();
    for (int i = tid; i < 32 * 112; i += 256) {
        int r = i / 112, k4 = i - r * 112;
        float4 v = ((const float4*)(g_x + (size_t)(rb + r) * 448))[k4];
        int k = k4 * 4;
        v.x = v.x * sa[k]     + sb[k];
        v.y = v.y * sa[k + 1] + sb[k + 1];
        v.z = v.z * sa[k + 2] + sb[k + 2];
        v.w = v.w * sa[k + 3] + sb[k + 3];
        ((float4*)(sx + r * 448))[k4] = v;
    }
    __syncthreads();
    int j = jb + (tid & 127);
    int oo = tid >> 7;
    const float4* Wj = (const float4*)(g_W1Tm + (size_t)j * 448);
    float bj = b1[j];
    for (int oi = 0; oi < 2; oi++) {
        int o = oo * 2 + oi;
        float acc[8];
#pragma unroll
        for (int u = 0; u < 8; u++) acc[u] = bj;
#pragma unroll 4
        for (int k4 = 0; k4 < 112; k4++) {
            float4 w = Wj[k4];
#pragma unroll
            for (int u = 0; u < 8; u++) {
                float4 h = ((const float4*)(sx + (o * 8 + u) * 448))[k4];
                acc[u] += w.x * h.x + w.y * h.y + w.z * h.z + w.w * h.w;
            }
        }
#pragma unroll
        for (int u = 0; u < 8; u++)
            g_z1[(size_t)(rb + o * 8 + u) * 512 + j] = acc[u];
    }
}

// ---------------- MLP layer 2: z2 = leaky(BN1(z1)) @ W2 + b2  (grid 32 x 2) ----------------
__global__ void __launch_bounds__(256) k_mlp2(const float* __restrict__ b2) {
    extern __shared__ float sm[];
    float* sy = sm;                // 32*512
    float* sa = sy + 32 * 512;     // 512
    float* sb = sa + 512;          // 512
    int rb = blockIdx.x * 32, jb = blockIdx.y * 128, tid = threadIdx.x;
    for (int i = tid; i < 512; i += 256) { sa[i] = g_a1[i]; sb[i] = g_bp1[i]; }
    __syncthreads();
    for (int i = tid; i < 32 * 128; i += 256) {
        int r = i >> 7, k4 = i & 127;
        float4 v = ((const float4*)(g_z1 + (size_t)(rb + r) * 512))[k4];
        int k = k4 * 4;
        v.x = v.x * sa[k]     + sb[k];
        v.y = v.y * sa[k + 1] + sb[k + 1];
        v.z = v.z * sa[k + 2] + sb[k + 2];
        v.w = v.w * sa[k + 3] + sb[k + 3];
        v.x = v.x > 0.f ? v.x : 0.1f * v.x;
        v.y = v.y > 0.f ? v.y : 0.1f * v.y;
        v.z = v.z > 0.f ? v.z : 0.1f * v.z;
        v.w = v.w > 0.f ? v.w : 0.1f * v.w;
        ((float4*)(sy + r * 512))[k4] = v;
    }
    __syncthreads();
    int j = jb + (tid & 127);
    int oo = tid >> 7;
    const float4* Wj = (const float4*)(g_W2Tm + (size_t)j * 512);
    float bj = b2[j];
    for (int oi = 0; oi < 2; oi++) {
        int o = oo * 2 + oi;
        float acc[8];
#pragma unroll
        for (int u = 0; u < 8; u++) acc[u] = bj;
#pragma unroll 4
        for (int k4 = 0; k4 < 128; k4++) {
            float4 w = Wj[k4];
#pragma unroll
            for (int u = 0; u < 8; u++) {
                float4 h = ((const float4*)(sy + (o * 8 + u) * 512))[k4];
                acc[u] += w.x * h.x + w.y * h.y + w.z * h.z + w.w * h.w;
            }
        }
#pragma unroll
        for (int u = 0; u < 8; u++)
            g_z2[(size_t)(rb + o * 8 + u) * 256 + j] = acc[u];
    }
}

// ---------------- output: leaky(BN2(z2)) @ W3 + b3 ----------------
__global__ void __launch_bounds__(256) k_out(const float* __restrict__ w3, const float* __restrict__ b3,
                                             float* __restrict__ out) {
    __shared__ float r0[256], r1s[256];
    int b = blockIdx.x, tid = threadIdx.x;
    float v = g_z2[b * 256 + tid] * g_a2[tid] + g_bp2[tid];
    v = v > 0.f ? v : 0.1f * v;
    r0[tid]  = v * w3[tid * 2];
    r1s[tid] = v * w3[tid * 2 + 1];
    __syncthreads();
    for (int s = 128; s > 0; s >>= 1) {
        if (tid < s) { r0[tid] += r0[tid + s]; r1s[tid] += r1s[tid + s]; }
        __syncthreads();
    }
    if (tid == 0) {
        out[b * 2]     = r0[0]  + b3[0];
        out[b * 2 + 1] = r1s[0] + b3[1];
    }
}

// ---------------- launch ----------------
extern "C" void kernel_launch(void* const* d_in, const int* in_sizes, int n_in,
                              void* d_out, int out_size) {
    const int*   uid  = (const int*)d_in[0];
    const int*   mid  = (const int*)d_in[1];
    const int*   cat  = (const int*)d_in[2];
    const int*   hm   = (const int*)d_in[3];
    const int*   hc   = (const int*)d_in[4];
    const int*   mask = (const int*)d_in[5];
    const float* utab = (const float*)d_in[6];
    const float* mtab = (const float*)d_in[7];
    const float* ctab = (const float*)d_in[8];
    const float* lw1  = (const float*)d_in[9];
    const float* lb1  = (const float*)d_in[10];
    const float* lw2  = (const float*)d_in[11];
    const float* lb2  = (const float*)d_in[12];
    const float* lw3  = (const float*)d_in[13];
    const float* lb3  = (const float*)d_in[14];
    const float* bn0g = (const float*)d_in[15];
    const float* bn0b = (const float*)d_in[16];
    const float* mw1  = (const float*)d_in[17];
    const float* mb1  = (const float*)d_in[18];
    const float* bn1g = (const float*)d_in[19];
    const float* bn1b = (const float*)d_in[20];
    const float* mw2  = (const float*)d_in[21];
    const float* mb2  = (const float*)d_in[22];
    const float* bn2g = (const float*)d_in[23];
    const float* bn2b = (const float*)d_in[24];
    const float* mw3  = (const float*)d_in[25];
    const float* mb3  = (const float*)d_in[26];
    float* out = (float*)d_out;

    const int SMEMF = (32 * 448 + 448 * 2) * 4;
    const int SMEMH = (32 * 512 + 512 * 2) * 4;

    cudaFuncSetAttribute(k_lau_mma, cudaFuncAttributeMaxDynamicSharedMemorySize, SMEM_G);
    cudaFuncSetAttribute(k_mlp1,  cudaFuncAttributeMaxDynamicSharedMemorySize, SMEMF);
    cudaFuncSetAttribute(k_mlp2,  cudaFuncAttributeMaxDynamicSharedMemorySize, SMEMH);

    k_prep<<<480, 256>>>(lw1, lw2, mw1, mw2);
    k_curcb<<<BB, 256>>>(mid, cat, mtab, ctab, lb1);
    k_lau_mma<<<BB, NTL, SMEM_G>>>(hm, hc, mtab, ctab, lb2, lw3, lb3);
    k_softlau<<<BB, 256>>>(mask, uid, utab);
    k_bnstats<<<14, 256>>>(0, bn0g, bn0b);
    k_mlp1<<<dim3(32, 4), 256, SMEMF>>>(mb1);
    k_bnstats<<<16, 256>>>(1, bn1g, bn1b);
    k_mlp2<<<dim3(32, 2), 256, SMEMH>>>(mb2);
    k_bnstats<<<8, 256>>>(2, bn2g, bn2b);
    k_out<<<BB, 256>>>(mw3, mb3, out);
}